// round 1
// baseline (speedup 1.0000x reference)
#include <cuda_runtime.h>
#include <cstdint>
#include <cstddef>

// ---------------- problem constants (fixed shapes for this problem) -----
#define N_NODES   25
#define NODE_DIM  128
#define IN_F      256
#define K_TOT     384          // NODE_DIM + IN_F
#define OUT_F     256
#define N_COLS    512          // [W0 | W1] stacked along output dim
#define NEG_BIG   (-9e15f)

// GEMM tiling
#define BM 128
#define BN 128
#define BK 32
#define AS_STRIDE 36           // 128x32 A tile, padded rows -> conflict-free frag loads
#define BS_STRIDE 132          // 32x128 B tile, padded rows -> <=2-way conflicts
#define GEMM_SMEM_BYTES ((2*BM*AS_STRIDE + 2*BK*BS_STRIDE) * 4)   // 70656

// ---------------- device scratch (static: no runtime allocation) --------
__device__ float g_diag[N_NODES];
__device__ float g_off[N_NODES * N_NODES];     // adj with zeroed diagonal
__device__ float g_Wr[2 * K_TOT * OUT_F];      // tf32-rounded W
__device__ float g_H[(size_t)8192 * N_NODES * N_COLS];  // H = inp @ [W0|W1]

// ---------------- small helpers -----------------------------------------
__device__ __forceinline__ uint32_t f2tf32(float x) {
    uint32_t u;
    asm("cvt.rna.tf32.f32 %0, %1;" : "=r"(u) : "f"(x));
    return u;
}

__device__ __forceinline__ void cp_async16(float* dst_smem, const float* src_gmem) {
    uint32_t d = (uint32_t)__cvta_generic_to_shared(dst_smem);
    asm volatile("cp.async.cg.shared.global [%0], [%1], 16;\n" :: "r"(d), "l"(src_gmem));
}

__device__ __forceinline__ void mma_tf32(float c[4], const uint32_t a[4],
                                         uint32_t b0, uint32_t b1) {
    asm volatile(
        "mma.sync.aligned.m16n8k8.row.col.f32.tf32.tf32.f32 "
        "{%0,%1,%2,%3}, {%4,%5,%6,%7}, {%8,%9}, {%0,%1,%2,%3};\n"
        : "+f"(c[0]), "+f"(c[1]), "+f"(c[2]), "+f"(c[3])
        : "r"(a[0]), "r"(a[1]), "r"(a[2]), "r"(a[3]), "r"(b0), "r"(b1));
}

// ================= kernel 1: softmax of scattered edge logits + W round ==
__global__ void setup_kernel(const float* __restrict__ W,
                             const float* __restrict__ e,
                             const int*   __restrict__ rows,
                             const int*   __restrict__ cols,
                             int nnz) {
    // every block: round W to tf32 (so B operand needs no per-use cvt)
    const int total = 2 * K_TOT * OUT_F;
    for (int i = blockIdx.x * blockDim.x + threadIdx.x; i < total;
         i += gridDim.x * blockDim.x) {
        float v = W[i];
        g_Wr[i] = __uint_as_float(f2tf32(v));
    }

    if (blockIdx.x == 0) {
        __shared__ float lg[N_NODES * N_NODES];
        int t = threadIdx.x;
        for (int i = t; i < N_NODES * N_NODES; i += blockDim.x) lg[i] = NEG_BIG;
        __syncthreads();
        for (int i = t; i < nnz; i += blockDim.x) lg[rows[i] * N_NODES + cols[i]] = e[i];
        __syncthreads();
        if (t < N_NODES) {
            float mx = -1e30f;
            #pragma unroll
            for (int n = 0; n < N_NODES; n++) mx = fmaxf(mx, lg[t * N_NODES + n]);
            float ex[N_NODES];
            float s = 0.f;
            #pragma unroll
            for (int n = 0; n < N_NODES; n++) {
                ex[n] = expf(lg[t * N_NODES + n] - mx);   // exp(NEG_BIG - mx) -> 0
                s += ex[n];
            }
            float inv = 1.f / s;
            #pragma unroll
            for (int n = 0; n < N_NODES; n++) {
                float a = ex[n] * inv;
                if (n == t) { g_diag[t] = a; g_off[t * N_NODES + n] = 0.f; }
                else        { g_off[t * N_NODES + n] = a; }
            }
        }
    }
}

// ================= kernel 2: H = inp @ [W0|W1]  (tf32 mma) ===============
// inp row r (= b*25+m): k<128 from node_vector (row stride 128),
//                       k>=128 from hidden_state (row stride 256).
// Each K-tile (32 wide) lies entirely in one source.
__global__ void __launch_bounds__(256, 2)
gemm_kernel(const float* __restrict__ nodev, const float* __restrict__ hid,
            int m_tiles) {
    extern __shared__ float smem[];
    float* As = smem;                          // [2][BM][AS_STRIDE]
    float* Bs = smem + 2 * BM * AS_STRIDE;     // [2][BK][BS_STRIDE]

    const int bx     = blockIdx.x;
    const int tile_m = bx >> 2;
    const int tile_n = bx & 3;
    const int tid    = threadIdx.x;
    const int warp   = tid >> 5;
    const int lane   = tid & 31;
    const int wm     = warp >> 2;              // 0..1  (64-row slabs)
    const int wn     = warp & 3;               // 0..3  (32-col slabs)
    const int lr     = lane >> 2;              // 0..7
    const int lc     = lane & 3;               // 0..3

    const int row0   = tile_m * BM;
    const float* Bbase = g_Wr + (tile_n >= 2 ? (K_TOT * OUT_F) : 0);
    const int jbase  = (tile_n & 1) * 128;

    float acc[4][4][4];
    #pragma unroll
    for (int i = 0; i < 4; i++)
        #pragma unroll
        for (int j = 0; j < 4; j++)
            #pragma unroll
            for (int k = 0; k < 4; k++) acc[i][j][k] = 0.f;

    // -------- tile loader (cp.async, 16B) --------
    const int a_m0 = tid >> 3;          // + i*32
    const int a_c  = (tid & 7) * 4;
    const int b_k0 = tid >> 5;          // + i*8
    const int b_c  = (tid & 31) * 4;

    #define LOAD_TILES(KT, BUF)                                                   \
    {                                                                             \
        const int k0 = (KT) * BK;                                                 \
        const float* aptr; int astride;                                           \
        if (k0 < NODE_DIM) { aptr = nodev + (size_t)row0 * NODE_DIM + k0;         \
                             astride = NODE_DIM; }                                \
        else               { aptr = hid + (size_t)row0 * IN_F + (k0 - NODE_DIM);  \
                             astride = IN_F; }                                    \
        float* asb = As + (BUF) * BM * AS_STRIDE;                                 \
        _Pragma("unroll")                                                         \
        for (int i = 0; i < 4; i++) {                                             \
            int m = i * 32 + a_m0;                                                \
            cp_async16(asb + m * AS_STRIDE + a_c,                                 \
                       aptr + (size_t)m * astride + a_c);                         \
        }                                                                         \
        float* bsb = Bs + (BUF) * BK * BS_STRIDE;                                 \
        _Pragma("unroll")                                                         \
        for (int i = 0; i < 4; i++) {                                             \
            int k = i * 8 + b_k0;                                                 \
            cp_async16(bsb + k * BS_STRIDE + b_c,                                 \
                       Bbase + (size_t)(k0 + k) * OUT_F + jbase + b_c);           \
        }                                                                         \
        asm volatile("cp.async.commit_group;\n");                                 \
    }

    LOAD_TILES(0, 0)

    const int NKT = K_TOT / BK;   // 12
    #pragma unroll 1
    for (int kt = 0; kt < NKT; kt++) {
        const int buf = kt & 1;
        asm volatile("cp.async.wait_group 0;\n");
        __syncthreads();
        if (kt + 1 < NKT) LOAD_TILES(kt + 1, buf ^ 1)

        const float* asb = As + buf * BM * AS_STRIDE + (wm * 64) * AS_STRIDE;
        const float* bsb = Bs + buf * BK * BS_STRIDE + wn * 32;

        #pragma unroll
        for (int ks = 0; ks < 4; ks++) {
            const int kk = ks * 8 + lc;
            uint32_t a[4][4];
            #pragma unroll
            for (int mf = 0; mf < 4; mf++) {
                const float* ap = asb + (mf * 16 + lr) * AS_STRIDE + kk;
                a[mf][0] = f2tf32(ap[0]);
                a[mf][1] = f2tf32(ap[8 * AS_STRIDE]);
                a[mf][2] = f2tf32(ap[4]);
                a[mf][3] = f2tf32(ap[8 * AS_STRIDE + 4]);
            }
            uint32_t b[4][2];
            #pragma unroll
            for (int nf = 0; nf < 4; nf++) {
                const float* bp = bsb + kk * BS_STRIDE + nf * 8 + lr;
                b[nf][0] = __float_as_uint(bp[0]);                 // pre-rounded
                b[nf][1] = __float_as_uint(bp[4 * BS_STRIDE]);
            }
            #pragma unroll
            for (int mf = 0; mf < 4; mf++)
                #pragma unroll
                for (int nf = 0; nf < 4; nf++)
                    mma_tf32(acc[mf][nf], a[mf], b[nf][0], b[nf][1]);
        }
        __syncthreads();
    }
    #undef LOAD_TILES

    // -------- epilogue: write H fp32 --------
    const int r_base = row0 + wm * 64;
    const int j_base = tile_n * 128 + wn * 32;
    #pragma unroll
    for (int mf = 0; mf < 4; mf++) {
        #pragma unroll
        for (int nf = 0; nf < 4; nf++) {
            const int r = r_base + mf * 16 + lr;
            const int j = j_base + nf * 8 + lc * 2;
            float2* p0 = (float2*)(g_H + (size_t)r * N_COLS + j);
            *p0 = make_float2(acc[mf][nf][0], acc[mf][nf][1]);
            float2* p1 = (float2*)(g_H + (size_t)(r + 8) * N_COLS + j);
            *p1 = make_float2(acc[mf][nf][2], acc[mf][nf][3]);
        }
    }
    (void)m_tiles;
}

// ================= kernel 3: mix + bias ==================================
// out[b,m,o] = diag[m]*H[b,m,o] + sum_n off[m,n]*H[b,n,256+o] + bias[o]
__global__ void __launch_bounds__(64)
mix_kernel(const float* __restrict__ bias, float* __restrict__ out) {
    __shared__ float h1s[N_NODES][OUT_F];          // 25.6 KB
    __shared__ float coff[N_NODES * N_NODES];
    __shared__ float cdia[N_NODES];

    const int b = blockIdx.x;
    const int t = threadIdx.x;
    const float* Hb = g_H + (size_t)b * (N_NODES * N_COLS);

    for (int i = t; i < N_NODES * N_NODES; i += 64) coff[i] = g_off[i];
    if (t < N_NODES) cdia[t] = g_diag[t];

    #pragma unroll 1
    for (int n = 0; n < N_NODES; n++) {
        float4 v = *(const float4*)(Hb + n * N_COLS + OUT_F + t * 4);
        *(float4*)(&h1s[n][t * 4]) = v;
    }
    __syncthreads();

    const int o = t * 4;
    float4 acc[N_NODES];
    #pragma unroll
    for (int m = 0; m < N_NODES; m++) {
        float4 h0 = *(const float4*)(Hb + m * N_COLS + o);
        float d = cdia[m];
        acc[m] = make_float4(d * h0.x, d * h0.y, d * h0.z, d * h0.w);
    }

    #pragma unroll 1
    for (int n = 0; n < N_NODES; n++) {
        float4 v = *(const float4*)(&h1s[n][o]);
        #pragma unroll
        for (int m = 0; m < N_NODES; m++) {
            float c = coff[m * N_NODES + n];
            acc[m].x += c * v.x;
            acc[m].y += c * v.y;
            acc[m].z += c * v.z;
            acc[m].w += c * v.w;
        }
    }

    const float4 bv = *(const float4*)(bias + o);
    float* ob = out + (size_t)b * (N_NODES * OUT_F);
    #pragma unroll
    for (int m = 0; m < N_NODES; m++) {
        float4 r = make_float4(acc[m].x + bv.x, acc[m].y + bv.y,
                               acc[m].z + bv.z, acc[m].w + bv.w);
        *(float4*)(ob + m * OUT_F + o) = r;
    }
}

// ================= launcher ==============================================
extern "C" void kernel_launch(void* const* d_in, const int* in_sizes, int n_in,
                              void* d_out, int out_size) {
    const float* nodev = (const float*)d_in[0];
    const float* hid   = (const float*)d_in[1];
    const float* W     = (const float*)d_in[2];
    const float* e     = (const float*)d_in[3];
    const float* bias  = (const float*)d_in[4];
    const int*   rows  = (const int*)d_in[5];
    const int*   cols  = (const int*)d_in[6];

    const int nnz = in_sizes[3];
    const int B   = in_sizes[0] / (N_NODES * NODE_DIM);   // 8192
    const int M   = B * N_NODES;                          // 204800
    const int m_tiles = M / BM;                           // 1600 (exact)

    setup_kernel<<<64, 256>>>(W, e, rows, cols, nnz);

    cudaFuncSetAttribute(gemm_kernel,
                         cudaFuncAttributeMaxDynamicSharedMemorySize,
                         GEMM_SMEM_BYTES);
    gemm_kernel<<<m_tiles * 4, 256, GEMM_SMEM_BYTES>>>(nodev, hid, m_tiles);

    mix_kernel<<<B, 64>>>(bias, (float*)d_out);
    (void)n_in; (void)out_size;
}

// round 2
// speedup vs baseline: 1.0065x; 1.0065x over previous
#include <cuda_runtime.h>
#include <cstdint>
#include <cstddef>

// ---------------- problem constants (fixed shapes for this problem) -----
#define N_NODES   25
#define NODE_DIM  128
#define IN_F      256
#define K_TOT     384          // NODE_DIM + IN_F
#define OUT_F     256
#define N_COLS    512          // [W0 | W1] stacked along output dim
#define NEG_BIG   (-9e15f)

// GEMM tiling
#define BM 128
#define BN 128
#define BK 32
#define AS_STRIDE 36           // 128x32 A tile, padded rows -> conflict-free frag loads
#define BS_STRIDE 132          // 32x128 B tile, padded rows -> <=2-way conflicts
#define GEMM_SMEM_BYTES ((2*BM*AS_STRIDE + 2*BK*BS_STRIDE) * 4)   // 70656

// ---------------- device scratch (static: no runtime allocation) --------
__device__ float g_diag[N_NODES];
__device__ float g_off[N_NODES * N_NODES];     // adj with zeroed diagonal
__device__ float g_Wr[2 * K_TOT * OUT_F];      // tf32-rounded W
__device__ float g_H[(size_t)8192 * N_NODES * N_COLS];  // H = inp @ [W0|W1]

// ---------------- small helpers -----------------------------------------
__device__ __forceinline__ uint32_t f2tf32(float x) {
    uint32_t u;
    asm("cvt.rna.tf32.f32 %0, %1;" : "=r"(u) : "f"(x));
    return u;
}

__device__ __forceinline__ void cp_async16(float* dst_smem, const float* src_gmem) {
    uint32_t d = (uint32_t)__cvta_generic_to_shared(dst_smem);
    asm volatile("cp.async.cg.shared.global [%0], [%1], 16;\n" :: "r"(d), "l"(src_gmem));
}

__device__ __forceinline__ void mma_tf32(float c[4], const uint32_t a[4],
                                         uint32_t b0, uint32_t b1) {
    asm volatile(
        "mma.sync.aligned.m16n8k8.row.col.f32.tf32.tf32.f32 "
        "{%0,%1,%2,%3}, {%4,%5,%6,%7}, {%8,%9}, {%0,%1,%2,%3};\n"
        : "+f"(c[0]), "+f"(c[1]), "+f"(c[2]), "+f"(c[3])
        : "r"(a[0]), "r"(a[1]), "r"(a[2]), "r"(a[3]), "r"(b0), "r"(b1));
}

// ================= kernel 1: softmax of scattered edge logits + W round ==
__global__ void setup_kernel(const float* __restrict__ W,
                             const float* __restrict__ e,
                             const int*   __restrict__ rows,
                             const int*   __restrict__ cols,
                             int nnz) {
    // every block: round W to tf32 (so B operand needs no per-use cvt)
    const int total = 2 * K_TOT * OUT_F;
    for (int i = blockIdx.x * blockDim.x + threadIdx.x; i < total;
         i += gridDim.x * blockDim.x) {
        float v = W[i];
        g_Wr[i] = __uint_as_float(f2tf32(v));
    }

    if (blockIdx.x == 0) {
        __shared__ float lg[N_NODES * N_NODES];
        int t = threadIdx.x;
        for (int i = t; i < N_NODES * N_NODES; i += blockDim.x) lg[i] = NEG_BIG;
        __syncthreads();
        for (int i = t; i < nnz; i += blockDim.x) lg[rows[i] * N_NODES + cols[i]] = e[i];
        __syncthreads();
        if (t < N_NODES) {
            float mx = -1e30f;
            #pragma unroll
            for (int n = 0; n < N_NODES; n++) mx = fmaxf(mx, lg[t * N_NODES + n]);
            float ex[N_NODES];
            float s = 0.f;
            #pragma unroll
            for (int n = 0; n < N_NODES; n++) {
                ex[n] = expf(lg[t * N_NODES + n] - mx);   // exp(NEG_BIG - mx) -> 0
                s += ex[n];
            }
            float inv = 1.f / s;
            #pragma unroll
            for (int n = 0; n < N_NODES; n++) {
                float a = ex[n] * inv;
                if (n == t) { g_diag[t] = a; g_off[t * N_NODES + n] = 0.f; }
                else        { g_off[t * N_NODES + n] = a; }
            }
        }
    }
}

// ================= kernel 2: H = inp @ [W0|W1]  (tf32 mma) ===============
// inp row r (= b*25+m): k<128 from node_vector (row stride 128),
//                       k>=128 from hidden_state (row stride 256).
// Each K-tile (32 wide) lies entirely in one source.
__global__ void __launch_bounds__(256, 2)
gemm_kernel(const float* __restrict__ nodev, const float* __restrict__ hid,
            int m_tiles) {
    extern __shared__ float smem[];
    float* As = smem;                          // [2][BM][AS_STRIDE]
    float* Bs = smem + 2 * BM * AS_STRIDE;     // [2][BK][BS_STRIDE]

    const int bx     = blockIdx.x;
    const int tile_m = bx >> 2;
    const int tile_n = bx & 3;
    const int tid    = threadIdx.x;
    const int warp   = tid >> 5;
    const int lane   = tid & 31;
    const int wm     = warp >> 2;              // 0..1  (64-row slabs)
    const int wn     = warp & 3;               // 0..3  (32-col slabs)
    const int lr     = lane >> 2;              // 0..7
    const int lc     = lane & 3;               // 0..3

    const int row0   = tile_m * BM;
    const float* Bbase = g_Wr + (tile_n >= 2 ? (K_TOT * OUT_F) : 0);
    const int jbase  = (tile_n & 1) * 128;

    float acc[4][4][4];
    #pragma unroll
    for (int i = 0; i < 4; i++)
        #pragma unroll
        for (int j = 0; j < 4; j++)
            #pragma unroll
            for (int k = 0; k < 4; k++) acc[i][j][k] = 0.f;

    // -------- tile loader (cp.async, 16B) --------
    const int a_m0 = tid >> 3;          // + i*32
    const int a_c  = (tid & 7) * 4;
    const int b_k0 = tid >> 5;          // + i*8
    const int b_c  = (tid & 31) * 4;

    #define LOAD_TILES(KT, BUF)                                                   \
    {                                                                             \
        const int k0 = (KT) * BK;                                                 \
        const float* aptr; int astride;                                           \
        if (k0 < NODE_DIM) { aptr = nodev + (size_t)row0 * NODE_DIM + k0;         \
                             astride = NODE_DIM; }                                \
        else               { aptr = hid + (size_t)row0 * IN_F + (k0 - NODE_DIM);  \
                             astride = IN_F; }                                    \
        float* asb = As + (BUF) * BM * AS_STRIDE;                                 \
        _Pragma("unroll")                                                         \
        for (int i = 0; i < 4; i++) {                                             \
            int m = i * 32 + a_m0;                                                \
            cp_async16(asb + m * AS_STRIDE + a_c,                                 \
                       aptr + (size_t)m * astride + a_c);                         \
        }                                                                         \
        float* bsb = Bs + (BUF) * BK * BS_STRIDE;                                 \
        _Pragma("unroll")                                                         \
        for (int i = 0; i < 4; i++) {                                             \
            int k = i * 8 + b_k0;                                                 \
            cp_async16(bsb + k * BS_STRIDE + b_c,                                 \
                       Bbase + (size_t)(k0 + k) * OUT_F + jbase + b_c);           \
        }                                                                         \
        asm volatile("cp.async.commit_group;\n");                                 \
    }

    LOAD_TILES(0, 0)

    const int NKT = K_TOT / BK;   // 12
    #pragma unroll 1
    for (int kt = 0; kt < NKT; kt++) {
        const int buf = kt & 1;
        asm volatile("cp.async.wait_group 0;\n");
        __syncthreads();
        if (kt + 1 < NKT) LOAD_TILES(kt + 1, buf ^ 1)

        const float* asb = As + buf * BM * AS_STRIDE + (wm * 64) * AS_STRIDE;
        const float* bsb = Bs + buf * BK * BS_STRIDE + wn * 32;

        #pragma unroll
        for (int ks = 0; ks < 4; ks++) {
            const int kk = ks * 8 + lc;
            uint32_t a[4][4];
            #pragma unroll
            for (int mf = 0; mf < 4; mf++) {
                const float* ap = asb + (mf * 16 + lr) * AS_STRIDE + kk;
                a[mf][0] = f2tf32(ap[0]);
                a[mf][1] = f2tf32(ap[8 * AS_STRIDE]);
                a[mf][2] = f2tf32(ap[4]);
                a[mf][3] = f2tf32(ap[8 * AS_STRIDE + 4]);
            }
            uint32_t b[4][2];
            #pragma unroll
            for (int nf = 0; nf < 4; nf++) {
                const float* bp = bsb + kk * BS_STRIDE + nf * 8 + lr;
                b[nf][0] = __float_as_uint(bp[0]);                 // pre-rounded
                b[nf][1] = __float_as_uint(bp[4 * BS_STRIDE]);
            }
            #pragma unroll
            for (int mf = 0; mf < 4; mf++)
                #pragma unroll
                for (int nf = 0; nf < 4; nf++)
                    mma_tf32(acc[mf][nf], a[mf], b[nf][0], b[nf][1]);
        }
        __syncthreads();
    }
    #undef LOAD_TILES

    // -------- epilogue: write H fp32 --------
    const int r_base = row0 + wm * 64;
    const int j_base = tile_n * 128 + wn * 32;
    #pragma unroll
    for (int mf = 0; mf < 4; mf++) {
        #pragma unroll
        for (int nf = 0; nf < 4; nf++) {
            const int r = r_base + mf * 16 + lr;
            const int j = j_base + nf * 8 + lc * 2;
            float2* p0 = (float2*)(g_H + (size_t)r * N_COLS + j);
            *p0 = make_float2(acc[mf][nf][0], acc[mf][nf][1]);
            float2* p1 = (float2*)(g_H + (size_t)(r + 8) * N_COLS + j);
            *p1 = make_float2(acc[mf][nf][2], acc[mf][nf][3]);
        }
    }
    (void)m_tiles;
}

// ================= kernel 3: mix + bias ==================================
// out[b,m,o] = diag[m]*H[b,m,o] + sum_n off[m,n]*H[b,n,256+o] + bias[o]
__global__ void __launch_bounds__(64)
mix_kernel(const float* __restrict__ bias, float* __restrict__ out) {
    __shared__ float h1s[N_NODES][OUT_F];          // 25.6 KB
    __shared__ float coff[N_NODES * N_NODES];
    __shared__ float cdia[N_NODES];

    const int b = blockIdx.x;
    const int t = threadIdx.x;
    const float* Hb = g_H + (size_t)b * (N_NODES * N_COLS);

    for (int i = t; i < N_NODES * N_NODES; i += 64) coff[i] = g_off[i];
    if (t < N_NODES) cdia[t] = g_diag[t];

    #pragma unroll 1
    for (int n = 0; n < N_NODES; n++) {
        float4 v = *(const float4*)(Hb + n * N_COLS + OUT_F + t * 4);
        *(float4*)(&h1s[n][t * 4]) = v;
    }
    __syncthreads();

    const int o = t * 4;
    float4 acc[N_NODES];
    #pragma unroll
    for (int m = 0; m < N_NODES; m++) {
        float4 h0 = *(const float4*)(Hb + m * N_COLS + o);
        float d = cdia[m];
        acc[m] = make_float4(d * h0.x, d * h0.y, d * h0.z, d * h0.w);
    }

    #pragma unroll 1
    for (int n = 0; n < N_NODES; n++) {
        float4 v = *(const float4*)(&h1s[n][o]);
        #pragma unroll
        for (int m = 0; m < N_NODES; m++) {
            float c = coff[m * N_NODES + n];
            acc[m].x += c * v.x;
            acc[m].y += c * v.y;
            acc[m].z += c * v.z;
            acc[m].w += c * v.w;
        }
    }

    const float4 bv = *(const float4*)(bias + o);
    float* ob = out + (size_t)b * (N_NODES * OUT_F);
    #pragma unroll
    for (int m = 0; m < N_NODES; m++) {
        float4 r = make_float4(acc[m].x + bv.x, acc[m].y + bv.y,
                               acc[m].z + bv.z, acc[m].w + bv.w);
        *(float4*)(ob + m * OUT_F + o) = r;
    }
}

// ================= launcher ==============================================
extern "C" void kernel_launch(void* const* d_in, const int* in_sizes, int n_in,
                              void* d_out, int out_size) {
    const float* nodev = (const float*)d_in[0];
    const float* hid   = (const float*)d_in[1];
    const float* W     = (const float*)d_in[2];
    const float* e     = (const float*)d_in[3];
    const float* bias  = (const float*)d_in[4];
    const int*   rows  = (const int*)d_in[5];
    const int*   cols  = (const int*)d_in[6];

    const int nnz = in_sizes[3];
    const int B   = in_sizes[0] / (N_NODES * NODE_DIM);   // 8192
    const int M   = B * N_NODES;                          // 204800
    const int m_tiles = M / BM;                           // 1600 (exact)

    setup_kernel<<<64, 256>>>(W, e, rows, cols, nnz);

    cudaFuncSetAttribute(gemm_kernel,
                         cudaFuncAttributeMaxDynamicSharedMemorySize,
                         GEMM_SMEM_BYTES);
    gemm_kernel<<<m_tiles * 4, 256, GEMM_SMEM_BYTES>>>(nodev, hid, m_tiles);

    mix_kernel<<<B, 64>>>(bias, (float*)d_out);
    (void)n_in; (void)out_size;
}